// round 7
// baseline (speedup 1.0000x reference)
#include <cuda_runtime.h>
#include <cstdint>

#define H 1024
#define T 1024
#define NE 16
#define IT 512
#define IV 256

// ---------------- scratch ----------------
__device__ float d_G[T * H];
__device__ float d_act[2 * T * IT];
__device__ float d_yp[2 * T * H];
__device__ int   d_pairs[2][NE][T];
__device__ int   d_cnt[2][NE];
__device__ float d_wts[T][2];
__device__ int   d_sel[T][2];
__device__ int   d_modal[T];

// ---------------- helpers ----------------
__device__ __forceinline__ uint32_t f2tf(float f) {
    uint32_t r;
    asm("cvt.rna.tf32.f32 %0, %1;" : "=r"(r) : "f"(f));
    return r;
}
__device__ __forceinline__ int swz(int r) { return (r + (r >> 2)) & 3; }

__device__ __forceinline__ void mma_tf32(float* c, const uint32_t* a, uint32_t b0, uint32_t b1) {
    asm volatile(
        "mma.sync.aligned.m16n8k8.row.col.f32.tf32.tf32.f32 "
        "{%0,%1,%2,%3}, {%4,%5,%6,%7}, {%8,%9}, {%0,%1,%2,%3};"
        : "+f"(c[0]), "+f"(c[1]), "+f"(c[2]), "+f"(c[3])
        : "r"(a[0]), "r"(a[1]), "r"(a[2]), "r"(a[3]), "r"(b0), "r"(b1));
}

// ---------------- router ----------------
__global__ __launch_bounds__(256) void k_router(
    const float* __restrict__ x, const int* __restrict__ tt,
    const float* __restrict__ Wt, const float* __restrict__ bt,
    const float* __restrict__ Wv, const float* __restrict__ bv,
    float* __restrict__ logits_out)
{
    int lane = threadIdx.x & 31;
    int t = blockIdx.x * 8 + (threadIdx.x >> 5);
    if (t >= T) return;

    int mod = (tt[t] != 0) ? 1 : 0;
    const float* W = mod ? Wv : Wt;
    const float* bias = mod ? bv : bt;

    float xr[32];
#pragma unroll
    for (int j = 0; j < 32; ++j) xr[j] = x[(size_t)t * H + lane + 32 * j];

    float logit[NE];
#pragma unroll
    for (int e = 0; e < NE; ++e) {
        const float* w = W + (size_t)e * H;
        float s = 0.f;
#pragma unroll
        for (int j = 0; j < 32; ++j) s = fmaf(xr[j], w[lane + 32 * j], s);
#pragma unroll
        for (int o = 16; o; o >>= 1) s += __shfl_xor_sync(0xffffffffu, s, o);
        logit[e] = s;
    }

    float mx = logit[0];
#pragma unroll
    for (int e = 1; e < NE; ++e) mx = fmaxf(mx, logit[e]);
    float p[NE], sum = 0.f;
#pragma unroll
    for (int e = 0; e < NE; ++e) { p[e] = expf(logit[e] - mx); sum += p[e]; }
    float inv = 1.f / sum;
#pragma unroll
    for (int e = 0; e < NE; ++e) p[e] *= inv;

    int i0 = 0; float b0 = -1e30f;
#pragma unroll
    for (int e = 0; e < NE; ++e) { float sc = p[e] + bias[e]; if (sc > b0) { b0 = sc; i0 = e; } }
    int i1 = 0; float b1 = -1e30f;
#pragma unroll
    for (int e = 0; e < NE; ++e) {
        if (e == i0) continue;
        float sc = p[e] + bias[e];
        if (sc > b1) { b1 = sc; i1 = e; }
    }
    float w0 = p[i0], w1 = p[i1];
    float s2 = fmaxf(w0 + w1, 1e-12f);
    w0 /= s2; w1 /= s2;

    if (lane < NE) logits_out[(size_t)t * NE + lane] = logit[lane];
    if (lane == 0) {
        d_sel[t][0] = i0; d_sel[t][1] = i1;
        d_wts[t][0] = w0; d_wts[t][1] = w1;
        d_modal[t] = mod;
    }
}

// ---------------- deterministic list build ----------------
__global__ __launch_bounds__(1024) void k_build() {
    int w = threadIdx.x >> 5, lane = threadIdx.x & 31;
    int mod = w >> 4, e = w & 15;
    int cnt = 0;
    for (int base = 0; base < T; base += 32) {
        int t = base + lane;
        int match = 0, slot = 0;
        if (d_modal[t] == mod) {
            if (d_sel[t][0] == e) { match = 1; slot = 0; }
            else if (d_sel[t][1] == e) { match = 1; slot = 1; }
        }
        unsigned m = __ballot_sync(0xffffffffu, match);
        if (match) {
            int pos = cnt + __popc(m & ((1u << lane) - 1u));
            d_pairs[mod][e][pos] = (t << 1) | slot;
        }
        cnt += __popc(m);
    }
    if (lane == 0) d_cnt[mod][e] = cnt;
}

// ---------------- tf32 GEMM core: 64x64 tile, BK=32, 4 warps ----------------
// GMODE: 0 direct rows; 1 A row = pair>>1, C row = pair; 2 A row = C row = pair
template <int GMODE, bool DUAL, bool SILU>
__device__ __forceinline__ void gemm_core(
    const float* __restrict__ A, int lda,
    const float* __restrict__ B0, const float* __restrict__ B1, int ldb,
    float* __restrict__ C, int ldc,
    int K, int mbase, int nbase,
    const int* __restrict__ plist, int cnt)
{
    __shared__ uint32_t As[2][2][64][16];
    __shared__ uint32_t Bs0[2][2][64][16];
    __shared__ uint32_t Bs1[DUAL ? 2 : 1][2][64][16];
    __shared__ int rowid[64];

    const int tid = threadIdx.x;
    const int lane = tid & 31;
    const int warp = tid >> 5;
    const int wm = warp & 1, wn = warp >> 1;
    const int g = lane >> 2, tg = lane & 3;

    if (GMODE != 0) {
        if (tid < 64) {
            int m = mbase + tid;
            rowid[tid] = (m < cnt) ? plist[m] : -1;
        }
        __syncthreads();
    }

    // A: f = tid + 128j -> m = f>>2, kq = f&3
    const float* aptr[2];
    int am[2], akq[2];
#pragma unroll
    for (int j = 0; j < 2; ++j) {
        int f = tid + 128 * j;
        int m = f >> 2;
        int kq = f & 3;
        am[j] = m; akq[j] = kq;
        int r;
        if (GMODE == 0) r = mbase + m;
        else {
            int pv = rowid[m];
            if (pv < 0) pv = 0;
            r = (GMODE == 1) ? (pv >> 1) : pv;
        }
        aptr[j] = A + (size_t)r * lda + kq * 4;
    }
    // B: f -> kb = f>>4 (0..15), n4 = (f&15)*4
    const float* b0ptr[2];
    const float* b1ptr[2];
    int bk[2], bn4[2];
#pragma unroll
    for (int j = 0; j < 2; ++j) {
        int f = tid + 128 * j;
        int kb = f >> 4;
        int n4 = (f & 15) * 4;
        bk[j] = kb; bn4[j] = n4;
        b0ptr[j] = B0 + (size_t)kb * ldb + nbase + n4;
        b1ptr[j] = DUAL ? (B1 + (size_t)kb * ldb + nbase + n4) : nullptr;
    }

    float acc0[2][4][4];
    float acc1[2][4][4];
#pragma unroll
    for (int a = 0; a < 2; ++a)
#pragma unroll
        for (int b = 0; b < 4; ++b)
#pragma unroll
            for (int c = 0; c < 4; ++c) { acc0[a][b][c] = 0.f; acc1[a][b][c] = 0.f; }

    float4 ar[2][2], b0r[2][2], b1r[2][2];

    auto LDG = [&](int kt) {
        size_t ka = (size_t)kt * 32;
#pragma unroll
        for (int h2 = 0; h2 < 2; ++h2) {
            size_t ko = ka + h2 * 16;
#pragma unroll
            for (int j = 0; j < 2; ++j) {
                ar[h2][j]  = *(const float4*)(aptr[j]  + ko);
                b0r[h2][j] = *(const float4*)(b0ptr[j] + ko * ldb);
                if (DUAL) b1r[h2][j] = *(const float4*)(b1ptr[j] + ko * ldb);
            }
        }
    };
    auto STS = [&](int buf) {
#pragma unroll
        for (int h2 = 0; h2 < 2; ++h2) {
#pragma unroll
            for (int j = 0; j < 2; ++j) {
                int m = am[j], kq = akq[j];
                int s = swz(m);
                const float v[4] = { ar[h2][j].x, ar[h2][j].y, ar[h2][j].z, ar[h2][j].w };
#pragma unroll
                for (int i = 0; i < 4; ++i)
                    As[buf][h2][m][((i ^ s) << 2) + kq] = f2tf(v[i]);
            }
#pragma unroll
            for (int j = 0; j < 2; ++j) {
                int k = bk[j], n4 = bn4[j];
                int jk = k & 3, wk = k >> 2;
                const float v0[4] = { b0r[h2][j].x, b0r[h2][j].y, b0r[h2][j].z, b0r[h2][j].w };
#pragma unroll
                for (int i = 0; i < 4; ++i)
                    Bs0[buf][h2][n4 + i][((jk ^ swz(n4 + i)) << 2) + wk] = f2tf(v0[i]);
                if (DUAL) {
                    const float v1[4] = { b1r[h2][j].x, b1r[h2][j].y, b1r[h2][j].z, b1r[h2][j].w };
#pragma unroll
                    for (int i = 0; i < 4; ++i)
                        Bs1[buf][h2][n4 + i][((jk ^ swz(n4 + i)) << 2) + wk] = f2tf(v1[i]);
                }
            }
        }
    };
    auto COMPUTE = [&](int buf) {
#pragma unroll
        for (int h2 = 0; h2 < 2; ++h2) {
            uint32_t Af[2][2][4];
#pragma unroll
            for (int fm = 0; fm < 2; ++fm)
#pragma unroll
                for (int rr = 0; rr < 2; ++rr) {
                    int m = wm * 32 + fm * 16 + g + rr * 8;
                    uint4 v = *(const uint4*)&As[buf][h2][m][(tg ^ swz(m)) << 2];
                    Af[fm][rr][0] = v.x; Af[fm][rr][1] = v.y;
                    Af[fm][rr][2] = v.z; Af[fm][rr][3] = v.w;
                }
            uint32_t Bf0[4][4], Bf1[4][4];
#pragma unroll
            for (int fn = 0; fn < 4; ++fn) {
                int n = wn * 32 + fn * 8 + g;
                uint4 v = *(const uint4*)&Bs0[buf][h2][n][(tg ^ swz(n)) << 2];
                Bf0[fn][0] = v.x; Bf0[fn][1] = v.y; Bf0[fn][2] = v.z; Bf0[fn][3] = v.w;
                if (DUAL) {
                    uint4 u = *(const uint4*)&Bs1[buf][h2][n][(tg ^ swz(n)) << 2];
                    Bf1[fn][0] = u.x; Bf1[fn][1] = u.y; Bf1[fn][2] = u.z; Bf1[fn][3] = u.w;
                }
            }
#pragma unroll
            for (int kk = 0; kk < 2; ++kk) {
                uint32_t a[2][4];
#pragma unroll
                for (int fm = 0; fm < 2; ++fm) {
                    a[fm][0] = Af[fm][0][2 * kk];
                    a[fm][1] = Af[fm][1][2 * kk];
                    a[fm][2] = Af[fm][0][2 * kk + 1];
                    a[fm][3] = Af[fm][1][2 * kk + 1];
                }
#pragma unroll
                for (int fn = 0; fn < 4; ++fn) {
                    uint32_t ba = Bf0[fn][2 * kk], bb = Bf0[fn][2 * kk + 1];
                    mma_tf32(acc0[0][fn], a[0], ba, bb);
                    mma_tf32(acc0[1][fn], a[1], ba, bb);
                    if (DUAL) {
                        uint32_t ca = Bf1[fn][2 * kk], cb = Bf1[fn][2 * kk + 1];
                        mma_tf32(acc1[0][fn], a[0], ca, cb);
                        mma_tf32(acc1[1][fn], a[1], ca, cb);
                    }
                }
            }
        }
    };

    int nk = K >> 5;
    LDG(0);
    STS(0);
    __syncthreads();
    for (int kt = 0; kt < nk; ++kt) {
        int cur = kt & 1;
        if (kt + 1 < nk) LDG(kt + 1);
        COMPUTE(cur);
        if (kt + 1 < nk) STS(cur ^ 1);
        __syncthreads();
    }

    // epilogue
#pragma unroll
    for (int fm = 0; fm < 2; ++fm) {
#pragma unroll
        for (int h = 0; h < 2; ++h) {
            int ml = wm * 32 + fm * 16 + g + h * 8;
            int crow;
            bool valid = true;
            if (GMODE != 0) {
                int pv = rowid[ml];
                valid = (pv >= 0);
                crow = pv;
            } else crow = mbase + ml;
            if (!valid) continue;
#pragma unroll
            for (int fn = 0; fn < 4; ++fn) {
                int nc = nbase + wn * 32 + fn * 8 + 2 * tg;
                float v0, v1;
                if (SILU) {
                    float g0 = acc0[fm][fn][2 * h], g1 = acc0[fm][fn][2 * h + 1];
                    v0 = (g0 / (1.f + __expf(-g0))) * acc1[fm][fn][2 * h];
                    v1 = (g1 / (1.f + __expf(-g1))) * acc1[fm][fn][2 * h + 1];
                } else {
                    v0 = acc0[fm][fn][2 * h];
                    v1 = acc0[fm][fn][2 * h + 1];
                }
                *(float2*)&C[(size_t)crow * ldc + nc] = make_float2(v0, v1);
            }
        }
    }
}

// ---------------- merged stage A: shared1 (z==32) + expert up (z<32) ----------------
__global__ __launch_bounds__(128) void k_stageA(
    const float* __restrict__ x, const float* __restrict__ sg, const float* __restrict__ su,
    const float* __restrict__ tgu, const float* __restrict__ vgu)
{
    int z = blockIdx.z;
    if (z == 32) {
        // shared1: M=1024 (grid.x=16), N=1024 (grid.y=16)
        gemm_core<0, true, true>(x, H, sg, su, H, d_G, H, H,
                                 blockIdx.x * 64, blockIdx.y * 64, nullptr, 0);
        return;
    }
    int mod = z >> 4, e = z & 15;
    int cnt = d_cnt[mod][e];
    int mbase = blockIdx.x * 64;
    if (mbase >= cnt) return;
    int I = mod ? IV : IT;
    int nbase = blockIdx.y * 64;
    if (nbase >= I) return;
    const float* gup = (mod ? vgu : tgu) + (size_t)e * H * 2 * I;
    gemm_core<1, true, true>(x, H, gup, gup + I, 2 * I, d_act, IT, H,
                             mbase, nbase, &d_pairs[mod][e][0], cnt);
}

// ---------------- merged stage B: shared2 (z==32) + expert down (z<32) ----------------
__global__ __launch_bounds__(128) void k_stageB(
    const float* __restrict__ sd, const float* __restrict__ tdn, const float* __restrict__ vdn,
    float* __restrict__ out)
{
    int z = blockIdx.z;
    if (z == 32) {
        gemm_core<0, false, false>(d_G, H, sd, nullptr, H, out, H, H,
                                   blockIdx.x * 64, blockIdx.y * 64, nullptr, 0);
        return;
    }
    int mod = z >> 4, e = z & 15;
    int cnt = d_cnt[mod][e];
    int mbase = blockIdx.x * 64;
    if (mbase >= cnt) return;
    int I = mod ? IV : IT;
    int nbase = blockIdx.y * 64;
    const float* dn = (mod ? vdn : tdn) + (size_t)e * I * H;
    gemm_core<2, false, false>(d_act, IT, dn, nullptr, H, d_yp, H, I,
                               mbase, nbase, &d_pairs[mod][e][0], cnt);
}

// ---------------- final combine ----------------
__global__ __launch_bounds__(256) void k_combine(float* __restrict__ out) {
    int gid = blockIdx.x * blockDim.x + threadIdx.x;   // float4 units
    int t = gid >> 8;
    int c4 = gid & 255;
    float w0 = d_wts[t][0], w1 = d_wts[t][1];
    float4 o = ((float4*)out)[gid];
    float4 a = ((const float4*)&d_yp[(size_t)(2 * t) * H])[c4];
    float4 b = ((const float4*)&d_yp[(size_t)(2 * t + 1) * H])[c4];
    o.x += w0 * a.x + w1 * b.x;
    o.y += w0 * a.y + w1 * b.y;
    o.z += w0 * a.z + w1 * b.z;
    o.w += w0 * a.w + w1 * b.w;
    ((float4*)out)[gid] = o;
}

// ---------------- launch ----------------
extern "C" void kernel_launch(void* const* d_in, const int* in_sizes, int n_in,
                              void* d_out, int out_size)
{
    const float* x   = (const float*)d_in[0];
    const int*   tt  = (const int*)d_in[1];
    const float* trw = (const float*)d_in[2];
    const float* tb  = (const float*)d_in[3];
    const float* tgu = (const float*)d_in[4];
    const float* tdn = (const float*)d_in[5];
    const float* vrw = (const float*)d_in[6];
    const float* vb  = (const float*)d_in[7];
    const float* vgu = (const float*)d_in[8];
    const float* vdn = (const float*)d_in[9];
    const float* sg  = (const float*)d_in[10];
    const float* su  = (const float*)d_in[11];
    const float* sd  = (const float*)d_in[12];

    float* out = (float*)d_out;
    float* logits = out + (size_t)T * H;

    k_router<<<128, 256>>>(x, tt, trw, tb, vrw, vb, logits);
    k_build<<<1, 1024>>>();
    k_stageA<<<dim3(16, 16, 33), 128>>>(x, sg, su, tgu, vgu);   // y=16: shared1 needs N=1024
    k_stageB<<<dim3(16, 16, 33), 128>>>(sd, tdn, vdn, out);
    k_combine<<<1024, 256>>>(out);
}

// round 8
// speedup vs baseline: 1.4227x; 1.4227x over previous
#include <cuda_runtime.h>
#include <cstdint>

#define H 1024
#define T 1024
#define NE 16
#define IT 512
#define IV 256

// ---------------- scratch ----------------
__device__ float d_G[T * H];
__device__ float d_act[2 * T * IT];
__device__ float d_yp[2 * T * H];
__device__ int   d_pairs[2][NE][T];
__device__ int   d_cnt[2][NE];
__device__ float d_wts[T][2];
__device__ int   d_sel[T][2];
__device__ int   d_modal[T];

// ---------------- helpers ----------------
__device__ __forceinline__ uint32_t f2tf(float f) {
    uint32_t r;
    asm("cvt.rna.tf32.f32 %0, %1;" : "=r"(r) : "f"(f));
    return r;
}
__device__ __forceinline__ int swz(int r) { return (r + (r >> 2)) & 3; }

__device__ __forceinline__ void mma_tf32(float* c, const uint32_t* a, uint32_t b0, uint32_t b1) {
    asm volatile(
        "mma.sync.aligned.m16n8k8.row.col.f32.tf32.tf32.f32 "
        "{%0,%1,%2,%3}, {%4,%5,%6,%7}, {%8,%9}, {%0,%1,%2,%3};"
        : "+f"(c[0]), "+f"(c[1]), "+f"(c[2]), "+f"(c[3])
        : "r"(a[0]), "r"(a[1]), "r"(a[2]), "r"(a[3]), "r"(b0), "r"(b1));
}

// ---------------- router ----------------
__global__ __launch_bounds__(256) void k_router(
    const float* __restrict__ x, const int* __restrict__ tt,
    const float* __restrict__ Wt, const float* __restrict__ bt,
    const float* __restrict__ Wv, const float* __restrict__ bv,
    float* __restrict__ logits_out)
{
    int lane = threadIdx.x & 31;
    int t = blockIdx.x * 8 + (threadIdx.x >> 5);
    if (t >= T) return;

    int mod = (tt[t] != 0) ? 1 : 0;
    const float* W = mod ? Wv : Wt;
    const float* bias = mod ? bv : bt;

    float xr[32];
#pragma unroll
    for (int j = 0; j < 32; ++j) xr[j] = x[(size_t)t * H + lane + 32 * j];

    float logit[NE];
#pragma unroll
    for (int e = 0; e < NE; ++e) {
        const float* w = W + (size_t)e * H;
        float s = 0.f;
#pragma unroll
        for (int j = 0; j < 32; ++j) s = fmaf(xr[j], w[lane + 32 * j], s);
#pragma unroll
        for (int o = 16; o; o >>= 1) s += __shfl_xor_sync(0xffffffffu, s, o);
        logit[e] = s;
    }

    float mx = logit[0];
#pragma unroll
    for (int e = 1; e < NE; ++e) mx = fmaxf(mx, logit[e]);
    float p[NE], sum = 0.f;
#pragma unroll
    for (int e = 0; e < NE; ++e) { p[e] = expf(logit[e] - mx); sum += p[e]; }
    float inv = 1.f / sum;
#pragma unroll
    for (int e = 0; e < NE; ++e) p[e] *= inv;

    int i0 = 0; float b0 = -1e30f;
#pragma unroll
    for (int e = 0; e < NE; ++e) { float sc = p[e] + bias[e]; if (sc > b0) { b0 = sc; i0 = e; } }
    int i1 = 0; float b1 = -1e30f;
#pragma unroll
    for (int e = 0; e < NE; ++e) {
        if (e == i0) continue;
        float sc = p[e] + bias[e];
        if (sc > b1) { b1 = sc; i1 = e; }
    }
    float w0 = p[i0], w1 = p[i1];
    float s2 = fmaxf(w0 + w1, 1e-12f);
    w0 /= s2; w1 /= s2;

    if (lane < NE) logits_out[(size_t)t * NE + lane] = logit[lane];
    if (lane == 0) {
        d_sel[t][0] = i0; d_sel[t][1] = i1;
        d_wts[t][0] = w0; d_wts[t][1] = w1;
        d_modal[t] = mod;
    }
}

// ---------------- deterministic list build ----------------
__global__ __launch_bounds__(1024) void k_build() {
    int w = threadIdx.x >> 5, lane = threadIdx.x & 31;
    int mod = w >> 4, e = w & 15;
    int cnt = 0;
    for (int base = 0; base < T; base += 32) {
        int t = base + lane;
        int match = 0, slot = 0;
        if (d_modal[t] == mod) {
            if (d_sel[t][0] == e) { match = 1; slot = 0; }
            else if (d_sel[t][1] == e) { match = 1; slot = 1; }
        }
        unsigned m = __ballot_sync(0xffffffffu, match);
        if (match) {
            int pos = cnt + __popc(m & ((1u << lane) - 1u));
            d_pairs[mod][e][pos] = (t << 1) | slot;
        }
        cnt += __popc(m);
    }
    if (lane == 0) d_cnt[mod][e] = cnt;
}

// ---------------- tf32 GEMM core: 64x64 tile, BK=16, 4 warps ----------------
// Single template instantiation per kernel; gmode is RUNTIME:
//   0 direct rows; 1 A row = pair>>1, C row = pair; 2 A row = C row = pair
template <bool DUAL, bool SILU>
__device__ __forceinline__ void gemm_core(
    int gmode,
    const float* __restrict__ A, int lda,
    const float* __restrict__ B0, const float* __restrict__ B1, int ldb,
    float* __restrict__ C, int ldc,
    int K, int mbase, int nbase,
    const int* __restrict__ plist, int cnt)
{
    __shared__ uint32_t As[2][64][16];
    __shared__ uint32_t Bs0[2][64][16];
    __shared__ uint32_t Bs1[DUAL ? 2 : 1][64][16];
    __shared__ int rowid[64];

    const int tid = threadIdx.x;
    const int lane = tid & 31;
    const int warp = tid >> 5;
    const int wm = warp & 1, wn = warp >> 1;
    const int g = lane >> 2, tg = lane & 3;

    if (gmode != 0) {
        if (tid < 64) {
            int m = mbase + tid;
            rowid[tid] = (m < cnt) ? plist[m] : -1;
        }
        __syncthreads();
    }

    // A: f = tid + 128j -> m = f>>2, kq = f&3
    const float* aptr[2];
    int am[2], akq[2];
#pragma unroll
    for (int j = 0; j < 2; ++j) {
        int f = tid + 128 * j;
        int m = f >> 2;
        int kq = f & 3;
        am[j] = m; akq[j] = kq;
        int r;
        if (gmode == 0) r = mbase + m;
        else {
            int pv = rowid[m];
            if (pv < 0) pv = 0;
            r = (gmode == 1) ? (pv >> 1) : pv;
        }
        aptr[j] = A + (size_t)r * lda + kq * 4;
    }
    // B: f -> kb = f>>4, n4 = (f&15)*4
    const float* b0ptr[2];
    const float* b1ptr[2];
    int bk[2], bn4[2];
#pragma unroll
    for (int j = 0; j < 2; ++j) {
        int f = tid + 128 * j;
        int kb = f >> 4;
        int n4 = (f & 15) * 4;
        bk[j] = kb; bn4[j] = n4;
        b0ptr[j] = B0 + (size_t)kb * ldb + nbase + n4;
        b1ptr[j] = DUAL ? (B1 + (size_t)kb * ldb + nbase + n4) : nullptr;
    }

    float acc0[2][4][4];
    float acc1[2][4][4];
#pragma unroll
    for (int a = 0; a < 2; ++a)
#pragma unroll
        for (int b = 0; b < 4; ++b)
#pragma unroll
            for (int c = 0; c < 4; ++c) { acc0[a][b][c] = 0.f; acc1[a][b][c] = 0.f; }

    float4 ar[2], b0r[2], b1r[2];

    auto LDG = [&](int kt) {
        size_t ka = (size_t)kt * 16;
#pragma unroll
        for (int j = 0; j < 2; ++j) {
            ar[j]  = *(const float4*)(aptr[j]  + ka);
            b0r[j] = *(const float4*)(b0ptr[j] + ka * ldb);
            if (DUAL) b1r[j] = *(const float4*)(b1ptr[j] + ka * ldb);
        }
    };
    auto STS = [&](int buf) {
#pragma unroll
        for (int j = 0; j < 2; ++j) {
            int m = am[j], kq = akq[j];
            int s = swz(m);
            const float v[4] = { ar[j].x, ar[j].y, ar[j].z, ar[j].w };
#pragma unroll
            for (int i = 0; i < 4; ++i)
                As[buf][m][((i ^ s) << 2) + kq] = f2tf(v[i]);
        }
#pragma unroll
        for (int j = 0; j < 2; ++j) {
            int k = bk[j], n4 = bn4[j];
            int jk = k & 3, wk = k >> 2;
            const float v0[4] = { b0r[j].x, b0r[j].y, b0r[j].z, b0r[j].w };
#pragma unroll
            for (int i = 0; i < 4; ++i)
                Bs0[buf][n4 + i][((jk ^ swz(n4 + i)) << 2) + wk] = f2tf(v0[i]);
            if (DUAL) {
                const float v1[4] = { b1r[j].x, b1r[j].y, b1r[j].z, b1r[j].w };
#pragma unroll
                for (int i = 0; i < 4; ++i)
                    Bs1[buf][n4 + i][((jk ^ swz(n4 + i)) << 2) + wk] = f2tf(v1[i]);
            }
        }
    };
    auto COMPUTE = [&](int buf) {
        uint32_t Af[2][2][4];
#pragma unroll
        for (int fm = 0; fm < 2; ++fm)
#pragma unroll
            for (int rr = 0; rr < 2; ++rr) {
                int m = wm * 32 + fm * 16 + g + rr * 8;
                uint4 v = *(const uint4*)&As[buf][m][(tg ^ swz(m)) << 2];
                Af[fm][rr][0] = v.x; Af[fm][rr][1] = v.y;
                Af[fm][rr][2] = v.z; Af[fm][rr][3] = v.w;
            }
        uint32_t Bf0[4][4], Bf1[4][4];
#pragma unroll
        for (int fn = 0; fn < 4; ++fn) {
            int n = wn * 32 + fn * 8 + g;
            uint4 v = *(const uint4*)&Bs0[buf][n][(tg ^ swz(n)) << 2];
            Bf0[fn][0] = v.x; Bf0[fn][1] = v.y; Bf0[fn][2] = v.z; Bf0[fn][3] = v.w;
            if (DUAL) {
                uint4 u = *(const uint4*)&Bs1[buf][n][(tg ^ swz(n)) << 2];
                Bf1[fn][0] = u.x; Bf1[fn][1] = u.y; Bf1[fn][2] = u.z; Bf1[fn][3] = u.w;
            }
        }
#pragma unroll
        for (int kk = 0; kk < 2; ++kk) {
            uint32_t a[2][4];
#pragma unroll
            for (int fm = 0; fm < 2; ++fm) {
                a[fm][0] = Af[fm][0][2 * kk];
                a[fm][1] = Af[fm][1][2 * kk];
                a[fm][2] = Af[fm][0][2 * kk + 1];
                a[fm][3] = Af[fm][1][2 * kk + 1];
            }
#pragma unroll
            for (int fn = 0; fn < 4; ++fn) {
                uint32_t ba = Bf0[fn][2 * kk], bb = Bf0[fn][2 * kk + 1];
                mma_tf32(acc0[0][fn], a[0], ba, bb);
                mma_tf32(acc0[1][fn], a[1], ba, bb);
                if (DUAL) {
                    uint32_t ca = Bf1[fn][2 * kk], cb = Bf1[fn][2 * kk + 1];
                    mma_tf32(acc1[0][fn], a[0], ca, cb);
                    mma_tf32(acc1[1][fn], a[1], ca, cb);
                }
            }
        }
    };

    int nk = K >> 4;
    LDG(0);
    STS(0);
    __syncthreads();
    for (int kt = 0; kt < nk; ++kt) {
        int cur = kt & 1;
        if (kt + 1 < nk) LDG(kt + 1);
        COMPUTE(cur);
        if (kt + 1 < nk) STS(cur ^ 1);
        __syncthreads();
    }

    // epilogue
#pragma unroll
    for (int fm = 0; fm < 2; ++fm) {
#pragma unroll
        for (int h = 0; h < 2; ++h) {
            int ml = wm * 32 + fm * 16 + g + h * 8;
            int crow;
            bool valid = true;
            if (gmode != 0) {
                int pv = rowid[ml];
                valid = (pv >= 0);
                crow = pv;
            } else crow = mbase + ml;
            if (!valid) continue;
#pragma unroll
            for (int fn = 0; fn < 4; ++fn) {
                int nc = nbase + wn * 32 + fn * 8 + 2 * tg;
                float v0, v1;
                if (SILU) {
                    float g0 = acc0[fm][fn][2 * h], g1 = acc0[fm][fn][2 * h + 1];
                    v0 = (g0 / (1.f + __expf(-g0))) * acc1[fm][fn][2 * h];
                    v1 = (g1 / (1.f + __expf(-g1))) * acc1[fm][fn][2 * h + 1];
                } else {
                    v0 = acc0[fm][fn][2 * h];
                    v1 = acc0[fm][fn][2 * h + 1];
                }
                *(float2*)&C[(size_t)crow * ldc + nc] = make_float2(v0, v1);
            }
        }
    }
}

// ---------------- merged stage A: z==0 shared1, z>=1 expert up ----------------
// Single instantiation <true,true>; gmode runtime.
__global__ __launch_bounds__(128) void k_stageA(
    const float* __restrict__ x, const float* __restrict__ sg, const float* __restrict__ su,
    const float* __restrict__ tgu, const float* __restrict__ vgu)
{
    int z = blockIdx.z;
    if (z == 0) {
        gemm_core<true, true>(0, x, H, sg, su, H, d_G, H, H,
                              blockIdx.x * 64, blockIdx.y * 64, nullptr, 0);
        return;
    }
    int ze = z - 1;
    int mod = ze >> 4, e = ze & 15;
    int cnt = d_cnt[mod][e];
    int mbase = blockIdx.x * 64;
    if (mbase >= cnt) return;
    int I = mod ? IV : IT;
    int nbase = blockIdx.y * 64;
    if (nbase >= I) return;
    const float* gup = (mod ? vgu : tgu) + (size_t)e * H * 2 * I;
    gemm_core<true, true>(1, x, H, gup, gup + I, 2 * I, d_act, IT, H,
                          mbase, nbase, &d_pairs[mod][e][0], cnt);
}

// ---------------- merged stage B: z==0 shared2, z>=1 expert down ----------------
__global__ __launch_bounds__(128) void k_stageB(
    const float* __restrict__ sd, const float* __restrict__ tdn, const float* __restrict__ vdn,
    float* __restrict__ out)
{
    int z = blockIdx.z;
    if (z == 0) {
        gemm_core<false, false>(0, d_G, H, sd, nullptr, H, out, H, H,
                                blockIdx.x * 64, blockIdx.y * 64, nullptr, 0);
        return;
    }
    int ze = z - 1;
    int mod = ze >> 4, e = ze & 15;
    int cnt = d_cnt[mod][e];
    int mbase = blockIdx.x * 64;
    if (mbase >= cnt) return;
    int I = mod ? IV : IT;
    int nbase = blockIdx.y * 64;
    const float* dn = (mod ? vdn : tdn) + (size_t)e * I * H;
    gemm_core<false, false>(2, d_act, IT, dn, nullptr, H, d_yp, H, I,
                            mbase, nbase, &d_pairs[mod][e][0], cnt);
}

// ---------------- final combine ----------------
__global__ __launch_bounds__(256) void k_combine(float* __restrict__ out) {
    int gid = blockIdx.x * blockDim.x + threadIdx.x;   // float4 units
    int t = gid >> 8;
    int c4 = gid & 255;
    float w0 = d_wts[t][0], w1 = d_wts[t][1];
    float4 o = ((float4*)out)[gid];
    float4 a = ((const float4*)&d_yp[(size_t)(2 * t) * H])[c4];
    float4 b = ((const float4*)&d_yp[(size_t)(2 * t + 1) * H])[c4];
    o.x += w0 * a.x + w1 * b.x;
    o.y += w0 * a.y + w1 * b.y;
    o.z += w0 * a.z + w1 * b.z;
    o.w += w0 * a.w + w1 * b.w;
    ((float4*)out)[gid] = o;
}

// ---------------- launch ----------------
extern "C" void kernel_launch(void* const* d_in, const int* in_sizes, int n_in,
                              void* d_out, int out_size)
{
    const float* x   = (const float*)d_in[0];
    const int*   tt  = (const int*)d_in[1];
    const float* trw = (const float*)d_in[2];
    const float* tb  = (const float*)d_in[3];
    const float* tgu = (const float*)d_in[4];
    const float* tdn = (const float*)d_in[5];
    const float* vrw = (const float*)d_in[6];
    const float* vb  = (const float*)d_in[7];
    const float* vgu = (const float*)d_in[8];
    const float* vdn = (const float*)d_in[9];
    const float* sg  = (const float*)d_in[10];
    const float* su  = (const float*)d_in[11];
    const float* sd  = (const float*)d_in[12];

    float* out = (float*)d_out;
    float* logits = out + (size_t)T * H;

    k_router<<<128, 256>>>(x, tt, trw, tb, vrw, vb, logits);
    k_build<<<1, 1024>>>();
    k_stageA<<<dim3(16, 16, 33), 128>>>(x, sg, su, tgu, vgu);
    k_stageB<<<dim3(16, 16, 33), 128>>>(sd, tdn, vdn, out);
    k_combine<<<1024, 256>>>(out);
}

// round 9
// speedup vs baseline: 1.7297x; 1.2157x over previous
#include <cuda_runtime.h>
#include <cstdint>

#define H 1024
#define T 1024
#define NE 16
#define IT 512
#define IV 256

// ---------------- scratch ----------------
__device__ float d_G[T * H];        // shared gate raw -> silu'd in place
__device__ float d_U[T * H];        // shared up raw
__device__ float d_eg[2 * T * IT];  // expert gate raw (stride IT)
__device__ float d_eu[2 * T * IT];  // expert up raw
__device__ float d_act[2 * T * IT]; // silu(eg)*eu
__device__ float d_yp[2 * T * H];   // per-pair expert outputs
__device__ int   d_pairs[2][NE][T];
__device__ int   d_cnt[2][NE];
__device__ float d_wts[T][2];
__device__ int   d_sel[T][2];
__device__ int   d_modal[T];

// ---------------- helpers ----------------
__device__ __forceinline__ uint32_t f2tf(float f) {
    uint32_t r;
    asm("cvt.rna.tf32.f32 %0, %1;" : "=r"(r) : "f"(f));
    return r;
}
__device__ __forceinline__ int swz(int r) { return (r + (r >> 2)) & 3; }

__device__ __forceinline__ void mma_tf32(float* c, const uint32_t* a, uint32_t b0, uint32_t b1) {
    asm volatile(
        "mma.sync.aligned.m16n8k8.row.col.f32.tf32.tf32.f32 "
        "{%0,%1,%2,%3}, {%4,%5,%6,%7}, {%8,%9}, {%0,%1,%2,%3};"
        : "+f"(c[0]), "+f"(c[1]), "+f"(c[2]), "+f"(c[3])
        : "r"(a[0]), "r"(a[1]), "r"(a[2]), "r"(a[3]), "r"(b0), "r"(b1));
}

// ---------------- router ----------------
__global__ __launch_bounds__(256) void k_router(
    const float* __restrict__ x, const int* __restrict__ tt,
    const float* __restrict__ Wt, const float* __restrict__ bt,
    const float* __restrict__ Wv, const float* __restrict__ bv,
    float* __restrict__ logits_out)
{
    int lane = threadIdx.x & 31;
    int t = blockIdx.x * 8 + (threadIdx.x >> 5);
    if (t >= T) return;

    int mod = (tt[t] != 0) ? 1 : 0;
    const float* W = mod ? Wv : Wt;
    const float* bias = mod ? bv : bt;

    float xr[32];
#pragma unroll
    for (int j = 0; j < 32; ++j) xr[j] = x[(size_t)t * H + lane + 32 * j];

    float logit[NE];
#pragma unroll
    for (int e = 0; e < NE; ++e) {
        const float* w = W + (size_t)e * H;
        float s = 0.f;
#pragma unroll
        for (int j = 0; j < 32; ++j) s = fmaf(xr[j], w[lane + 32 * j], s);
#pragma unroll
        for (int o = 16; o; o >>= 1) s += __shfl_xor_sync(0xffffffffu, s, o);
        logit[e] = s;
    }

    float mx = logit[0];
#pragma unroll
    for (int e = 1; e < NE; ++e) mx = fmaxf(mx, logit[e]);
    float p[NE], sum = 0.f;
#pragma unroll
    for (int e = 0; e < NE; ++e) { p[e] = expf(logit[e] - mx); sum += p[e]; }
    float inv = 1.f / sum;
#pragma unroll
    for (int e = 0; e < NE; ++e) p[e] *= inv;

    int i0 = 0; float b0 = -1e30f;
#pragma unroll
    for (int e = 0; e < NE; ++e) { float sc = p[e] + bias[e]; if (sc > b0) { b0 = sc; i0 = e; } }
    int i1 = 0; float b1 = -1e30f;
#pragma unroll
    for (int e = 0; e < NE; ++e) {
        if (e == i0) continue;
        float sc = p[e] + bias[e];
        if (sc > b1) { b1 = sc; i1 = e; }
    }
    float w0 = p[i0], w1 = p[i1];
    float s2 = fmaxf(w0 + w1, 1e-12f);
    w0 /= s2; w1 /= s2;

    if (lane < NE) logits_out[(size_t)t * NE + lane] = logit[lane];
    if (lane == 0) {
        d_sel[t][0] = i0; d_sel[t][1] = i1;
        d_wts[t][0] = w0; d_wts[t][1] = w1;
        d_modal[t] = mod;
    }
}

// ---------------- deterministic list build ----------------
__global__ __launch_bounds__(1024) void k_build() {
    int w = threadIdx.x >> 5, lane = threadIdx.x & 31;
    int mod = w >> 4, e = w & 15;
    int cnt = 0;
    for (int base = 0; base < T; base += 32) {
        int t = base + lane;
        int match = 0, slot = 0;
        if (d_modal[t] == mod) {
            if (d_sel[t][0] == e) { match = 1; slot = 0; }
            else if (d_sel[t][1] == e) { match = 1; slot = 1; }
        }
        unsigned m = __ballot_sync(0xffffffffu, match);
        if (match) {
            int pos = cnt + __popc(m & ((1u << lane) - 1u));
            d_pairs[mod][e][pos] = (t << 1) | slot;
        }
        cnt += __popc(m);
    }
    if (lane == 0) d_cnt[mod][e] = cnt;
}

// ============ tf32 GEMM core: 64(M) x 128(N) block, warp tile 32x64 ============
// All smem traffic is conflict-free STS.128 / LDS.128, with k-interleaved mma
// feeding (lane tg supplies global k = 4*tg + {0..3}).
// gmode: 0 direct rows; 1 A row = pair>>1, C row = pair; 2 A row = C row = pair
__device__ __forceinline__ void gemm_core(
    int gmode,
    const float* __restrict__ A, int lda,
    const float* __restrict__ B, int ldb,
    float* __restrict__ C, int ldc,
    int K, int mbase, int nbase,
    const int* __restrict__ plist, int cnt)
{
    __shared__ uint32_t As[2][64][16];    // [m][k-group swizzled]
    __shared__ uint32_t Bs[2][128][16];   // [n][k-group swizzled]
    __shared__ int rowid[64];

    const int tid = threadIdx.x;
    const int lane = tid & 31;
    const int warp = tid >> 5;
    const int wm = warp & 1, wn = warp >> 1;   // wm: m-half, wn: n-half
    const int g = lane >> 2, tg = lane & 3;

    if (gmode != 0) {
        if (tid < 64) {
            int m = mbase + tid;
            rowid[tid] = (m < cnt) ? plist[m] : -1;
        }
        __syncthreads();
    }

    // ---- A global pointers: f = tid + 128j -> m = f>>2, kq = f&3 ----
    const float* aptr[2];
    int am[2], akq[2];
#pragma unroll
    for (int j = 0; j < 2; ++j) {
        int f = tid + 128 * j;
        int m = f >> 2;
        int kq = f & 3;
        am[j] = m; akq[j] = kq;
        int r;
        if (gmode == 0) r = mbase + m;
        else {
            int pv = rowid[m];
            if (pv < 0) pv = 0;
            r = (gmode == 1) ? (pv >> 1) : pv;
        }
        aptr[j] = A + (size_t)r * lda + kq * 4;
    }

    // ---- B global pointer: warp supplies k-quad kqB = warp; lane -> n ----
    const int kqB = warp;          // 0..3 -> k = 4*kqB + j
    const int nl = lane;           // n = nl + 32*grp
    const float* bptr = B + (size_t)(4 * kqB) * ldb + nbase + nl;
    const size_t ldb1 = ldb, ldb2 = 2 * (size_t)ldb, ldb3 = 3 * (size_t)ldb;

    float acc[2][8][4];
#pragma unroll
    for (int a = 0; a < 2; ++a)
#pragma unroll
        for (int b = 0; b < 8; ++b)
#pragma unroll
            for (int c = 0; c < 4; ++c) acc[a][b][c] = 0.f;

    float4 ar[2];
    float bv[4][4];   // [grp][j]

    auto LDG = [&]() {
#pragma unroll
        for (int j = 0; j < 2; ++j) ar[j] = *(const float4*)(aptr[j]);
#pragma unroll
        for (int grp = 0; grp < 4; ++grp) {
            bv[grp][0] = bptr[grp * 32];
            bv[grp][1] = bptr[ldb1 + grp * 32];
            bv[grp][2] = bptr[ldb2 + grp * 32];
            bv[grp][3] = bptr[ldb3 + grp * 32];
        }
        aptr[0] += 16; aptr[1] += 16;
        bptr += 16 * ldb1;
    };
    auto STS = [&](int buf) {
#pragma unroll
        for (int j = 0; j < 2; ++j) {
            int m = am[j];
            uint4 w;
            w.x = f2tf(ar[j].x); w.y = f2tf(ar[j].y);
            w.z = f2tf(ar[j].z); w.w = f2tf(ar[j].w);
            *(uint4*)&As[buf][m][(akq[j] ^ swz(m)) << 2] = w;
        }
#pragma unroll
        for (int grp = 0; grp < 4; ++grp) {
            int n = nl + 32 * grp;
            uint4 w;
            w.x = f2tf(bv[grp][0]); w.y = f2tf(bv[grp][1]);
            w.z = f2tf(bv[grp][2]); w.w = f2tf(bv[grp][3]);
            *(uint4*)&Bs[buf][n][(kqB ^ swz(n)) << 2] = w;
        }
    };
    auto COMPUTE = [&](int buf) {
        // A fragments: rows wm*32 + fm*16 + g (+8); uint4 = global k 4tg..4tg+3
        uint32_t Af[2][2][4];
#pragma unroll
        for (int fm = 0; fm < 2; ++fm)
#pragma unroll
            for (int rr = 0; rr < 2; ++rr) {
                int m = wm * 32 + fm * 16 + g + rr * 8;
                uint4 v = *(const uint4*)&As[buf][m][(tg ^ swz(m)) << 2];
                Af[fm][rr][0] = v.x; Af[fm][rr][1] = v.y;
                Af[fm][rr][2] = v.z; Af[fm][rr][3] = v.w;
            }
        uint32_t Bf[8][4];
#pragma unroll
        for (int fn = 0; fn < 8; ++fn) {
            int n = wn * 64 + fn * 8 + g;
            uint4 v = *(const uint4*)&Bs[buf][n][(tg ^ swz(n)) << 2];
            Bf[fn][0] = v.x; Bf[fn][1] = v.y; Bf[fn][2] = v.z; Bf[fn][3] = v.w;
        }
        // k-interleave: mma kk uses global k = 4*tg + 2*kk + {0,1}
#pragma unroll
        for (int kk = 0; kk < 2; ++kk) {
            uint32_t a[2][4];
#pragma unroll
            for (int fm = 0; fm < 2; ++fm) {
                a[fm][0] = Af[fm][0][2 * kk];
                a[fm][1] = Af[fm][1][2 * kk];
                a[fm][2] = Af[fm][0][2 * kk + 1];
                a[fm][3] = Af[fm][1][2 * kk + 1];
            }
#pragma unroll
            for (int fn = 0; fn < 8; ++fn) {
                uint32_t b0 = Bf[fn][2 * kk], b1 = Bf[fn][2 * kk + 1];
                mma_tf32(acc[0][fn], a[0], b0, b1);
                mma_tf32(acc[1][fn], a[1], b0, b1);
            }
        }
    };

    int nk = K >> 4;
    LDG();
    STS(0);
    __syncthreads();
    for (int kt = 0; kt < nk; ++kt) {
        int cur = kt & 1;
        if (kt + 1 < nk) LDG();
        COMPUTE(cur);
        if (kt + 1 < nk) STS(cur ^ 1);
        __syncthreads();
    }

    // ---- epilogue ----
#pragma unroll
    for (int fm = 0; fm < 2; ++fm) {
#pragma unroll
        for (int h = 0; h < 2; ++h) {
            int ml = wm * 32 + fm * 16 + g + h * 8;
            int crow;
            bool valid = true;
            if (gmode != 0) {
                int pv = rowid[ml];
                valid = (pv >= 0);
                crow = pv;
            } else crow = mbase + ml;
            if (!valid) continue;
#pragma unroll
            for (int fn = 0; fn < 8; ++fn) {
                int nc = nbase + wn * 64 + fn * 8 + 2 * tg;
                *(float2*)&C[(size_t)crow * ldc + nc] =
                    make_float2(acc[fm][fn][2 * h], acc[fm][fn][2 * h + 1]);
            }
        }
    }
}

// ---------------- GEMM pass 1: shared gate/up + expert gate/up (all raw) ----------------
// z: 0 = shared gate, 1 = shared up, 2..33 = expert gate, 34..65 = expert up
__global__ __launch_bounds__(128) void k_gemm1(
    const float* __restrict__ x, const float* __restrict__ sg, const float* __restrict__ su,
    const float* __restrict__ tgu, const float* __restrict__ vgu)
{
    int z = blockIdx.z;
    int mbase = blockIdx.x * 64;
    int nbase = blockIdx.y * 128;
    if (z < 2) {
        const float* Bm = z ? su : sg;
        float* Cm = z ? d_U : d_G;
        gemm_core(0, x, H, Bm, H, Cm, H, H, mbase, nbase, nullptr, 0);
        return;
    }
    int isup = (z >= 34);
    int idx = z - (isup ? 34 : 2);
    int mod = idx >> 4, e = idx & 15;
    int cnt = d_cnt[mod][e];
    if (mbase >= cnt) return;
    int I = mod ? IV : IT;
    if (nbase >= I) return;
    const float* gup = (mod ? vgu : tgu) + (size_t)e * H * 2 * I + (isup ? I : 0);
    float* Cm = isup ? d_eu : d_eg;
    gemm_core(1, x, H, gup, 2 * I, Cm, IT, H,
              mbase, nbase, &d_pairs[mod][e][0], cnt);
}

// ---------------- elementwise silu-mul ----------------
// region 0: d_G = silu(d_G) * d_U            (T*H floats)
// region 1: d_act = silu(d_eg) * d_eu        (2T*IT floats)
__global__ __launch_bounds__(256) void k_silu() {
    int gid = blockIdx.x * blockDim.x + threadIdx.x;  // float4 units, 524288 total
    const int NG = (T * H) / 4;                       // 262144
    float4 gv, uv;
    float4* outp;
    if (gid < NG) {
        gv = ((const float4*)d_G)[gid];
        uv = ((const float4*)d_U)[gid];
        outp = &((float4*)d_G)[gid];
    } else {
        int p = gid - NG;
        gv = ((const float4*)d_eg)[p];
        uv = ((const float4*)d_eu)[p];
        outp = &((float4*)d_act)[p];
    }
    float4 o;
    o.x = (gv.x / (1.f + __expf(-gv.x))) * uv.x;
    o.y = (gv.y / (1.f + __expf(-gv.y))) * uv.y;
    o.z = (gv.z / (1.f + __expf(-gv.z))) * uv.z;
    o.w = (gv.w / (1.f + __expf(-gv.w))) * uv.w;
    *outp = o;
}

// ---------------- GEMM pass 2: shared down + expert down ----------------
// z: 0 = shared2 (G @ sd -> out), 1..32 = expert down
__global__ __launch_bounds__(128) void k_gemm2(
    const float* __restrict__ sd, const float* __restrict__ tdn, const float* __restrict__ vdn,
    float* __restrict__ out)
{
    int z = blockIdx.z;
    int mbase = blockIdx.x * 64;
    int nbase = blockIdx.y * 128;
    if (z == 0) {
        gemm_core(0, d_G, H, sd, H, out, H, H, mbase, nbase, nullptr, 0);
        return;
    }
    int idx = z - 1;
    int mod = idx >> 4, e = idx & 15;
    int cnt = d_cnt[mod][e];
    if (mbase >= cnt) return;
    int I = mod ? IV : IT;
    const float* dn = (mod ? vdn : tdn) + (size_t)e * I * H;
    gemm_core(2, d_act, IT, dn, H, d_yp, H, I,
              mbase, nbase, &d_pairs[mod][e][0], cnt);
}

// ---------------- final combine ----------------
__global__ __launch_bounds__(256) void k_combine(float* __restrict__ out) {
    int gid = blockIdx.x * blockDim.x + threadIdx.x;   // float4 units
    int t = gid >> 8;
    int c4 = gid & 255;
    float w0 = d_wts[t][0], w1 = d_wts[t][1];
    float4 o = ((float4*)out)[gid];
    float4 a = ((const float4*)&d_yp[(size_t)(2 * t) * H])[c4];
    float4 b = ((const float4*)&d_yp[(size_t)(2 * t + 1) * H])[c4];
    o.x += w0 * a.x + w1 * b.x;
    o.y += w0 * a.y + w1 * b.y;
    o.z += w0 * a.z + w1 * b.z;
    o.w += w0 * a.w + w1 * b.w;
    ((float4*)out)[gid] = o;
}

// ---------------- launch ----------------
extern "C" void kernel_launch(void* const* d_in, const int* in_sizes, int n_in,
                              void* d_out, int out_size)
{
    const float* x   = (const float*)d_in[0];
    const int*   tt  = (const int*)d_in[1];
    const float* trw = (const float*)d_in[2];
    const float* tb  = (const float*)d_in[3];
    const float* tgu = (const float*)d_in[4];
    const float* tdn = (const float*)d_in[5];
    const float* vrw = (const float*)d_in[6];
    const float* vb  = (const float*)d_in[7];
    const float* vgu = (const float*)d_in[8];
    const float* vdn = (const float*)d_in[9];
    const float* sg  = (const float*)d_in[10];
    const float* su  = (const float*)d_in[11];
    const float* sd  = (const float*)d_in[12];

    float* out = (float*)d_out;
    float* logits = out + (size_t)T * H;

    k_router<<<128, 256>>>(x, tt, trw, tb, vrw, vb, logits);
    k_build<<<1, 1024>>>();
    k_gemm1<<<dim3(16, 8, 66), 128>>>(x, sg, su, tgu, vgu);
    k_silu<<<2048, 256>>>();
    k_gemm2<<<dim3(16, 8, 33), 128>>>(sd, tdn, vdn, out);
    k_combine<<<1024, 256>>>(out);
}